// round 9
// baseline (speedup 1.0000x reference)
#include <cuda_runtime.h>
#include <cuda_fp16.h>
#include <cstdint>

// ---------------- problem constants ----------------
#define Nn   10000
#define KRr  5
#define KAa  8
#define Cc   32
#define Oo   64

#define Mdim 40000            // B*N
#define Kdim 1280             // KR*KA*C  (X-hat row width)
#define Mpad 40064            // 313 * 128

// ---------------- frequency-block GEMM tiling ----------------
#define KF   320                   // K per freq block
#define NF   128                   // N per freq block
#define NBLK 4                     // {f0|f4}, f1, f2, f3
#define KCHUNK 64                  // fp16 per K chunk (128 B per row)
#define NCHUNK_T (NBLK * KF / KCHUNK)  // 20 total chunks
#define B_OFF 16384
#define STAGE_BYTES 32768
#define NSTAGE 3
#define YSM_OFF (NSTAGE * STAGE_BYTES)          // 98304
#define FUSED_SMEM (YSM_OFF + 128 * 512 * 2)    // 229376 (<= 227KB limit)

#define SQH 0.70710678118654752f

// ---------------- device scratch ----------------
__device__ __half g_Xh[(size_t)Mpad * Kdim];        // X-hat fp16 (freq layout)
__device__ __half g_Wb[(size_t)NBLK * NF * KF];     // W-hat blocks [4][128][320]
__device__ __half g_Sh[(size_t)4 * Nn * Cc];        // signal fp16
__device__ float  g_biasK[Oo];

// ---------------- helpers ----------------
__device__ __forceinline__ uint32_t smem_u32(const void* p) {
    uint32_t a;
    asm("{ .reg .u64 t; cvta.to.shared.u64 t, %1; cvt.u32.u64 %0, t; }" : "=r"(a) : "l"(p));
    return a;
}
__device__ __forceinline__ void cp16(uint32_t dst, const void* src) {
    asm volatile("cp.async.cg.shared.global [%0], [%1], 16;" :: "r"(dst), "l"(src));
}
__device__ __forceinline__ void ldsm_x4(uint32_t addr, uint32_t& r0, uint32_t& r1,
                                        uint32_t& r2, uint32_t& r3) {
    asm volatile("ldmatrix.sync.aligned.m8n8.x4.shared.b16 {%0,%1,%2,%3}, [%4];"
                 : "=r"(r0), "=r"(r1), "=r"(r2), "=r"(r3) : "r"(addr));
}
__device__ __forceinline__ void mma16816(float* c, const uint32_t* a,
                                         uint32_t b0, uint32_t b1) {
    asm volatile(
        "mma.sync.aligned.m16n8k16.row.col.f32.f16.f16.f32 "
        "{%0,%1,%2,%3}, {%4,%5,%6,%7}, {%8,%9}, {%0,%1,%2,%3};"
        : "+f"(c[0]), "+f"(c[1]), "+f"(c[2]), "+f"(c[3])
        : "r"(a[0]), "r"(a[1]), "r"(a[2]), "r"(a[3]), "r"(b0), "r"(b1));
}

// 8-point real DFT: x[0..7] -> {X0, X4, Re1, Im1, Re2, Im2, Re3, Im3}
__device__ __forceinline__ void fft8(const float* x, float* o) {
    float p04 = x[0] + x[4], m04 = x[0] - x[4];
    float p26 = x[2] + x[6], m26 = x[2] - x[6];
    float pbd = x[1] + x[3], pfh = x[5] + x[7];
    float mbd = x[1] - x[3], mfh = x[5] - x[7];
    float sodd = pbd + pfh;
    float B1 = mbd - mfh;
    float B2 = pfh - pbd;
    o[0] = p04 + p26 + sodd;
    o[1] = p04 + p26 - sodd;
    o[2] = m04 + SQH * B1;
    o[3] = -m26 + SQH * B2;
    o[4] = p04 - p26;
    o[5] = -(mbd + mfh);
    o[6] = m04 - SQH * B1;
    o[7] = m26 + SQH * B2;
}

// ---------------------------------------------------------------------------
__global__ void conv_signal_kernel(const float* __restrict__ signal) {
    int i = blockIdx.x * blockDim.x + threadIdx.x;
    if (i >= (4 * Nn * Cc) / 4) return;
    float4 v = ((const float4*)signal)[i];
    __half2 h0 = __halves2half2(__float2half_rn(v.x), __float2half_rn(v.y));
    __half2 h1 = __halves2half2(__float2half_rn(v.z), __float2half_rn(v.w));
    ((__half2*)g_Sh)[2 * i]     = h0;
    ((__half2*)g_Sh)[2 * i + 1] = h1;
}

// ---------------------------------------------------------------------------
// Prep W-hat blocks (unchanged)
// ---------------------------------------------------------------------------
__global__ void prep_wb_kernel(const float* __restrict__ kernels) {
    const int row = blockIdx.x;            // 0..511
    const int g = row >> 7;
    const int np = row & 127;
    const int h = np >> 6, o = np & 63;
    const int kp = threadIdx.x;            // 0..319
    const int half = (kp >= 160) ? 1 : 0;
    const int kk = kp - 160 * half;
    const int p = kk >> 5, c = kk & 31;

    float wsum[8];
#pragma unroll
    for (int q = 0; q < 8; q++) {
        int base = p * 16384 + q * 2048 + o * 32 + c;
        wsum[q] = kernels[base] + kernels[81920 + base];
    }

    float val = 0.f;
    if (g == 0) {
        if (h == 0 && half == 0) {
#pragma unroll
            for (int q = 0; q < 8; q++) val += wsum[q];
        } else if (h == 1 && half == 1) {
#pragma unroll
            for (int q = 0; q < 8; q++) val += (q & 1) ? -wsum[q] : wsum[q];
        }
    } else {
        const float ct[8] = {1.f, SQH, 0.f, -SQH, -1.f, -SQH, 0.f, SQH};
        const float st[8] = {0.f, SQH, 1.f, SQH, 0.f, -SQH, -1.f, -SQH};
        float Wr = 0.f, Wi = 0.f;
#pragma unroll
        for (int q = 0; q < 8; q++) {
            int i = (g * q) & 7;
            Wr += wsum[q] * ct[i];
            Wi -= wsum[q] * st[i];
        }
        if (h == 0) val = half ? Wi : Wr;
        else        val = half ? -Wr : Wi;
    }
    g_Wb[(size_t)row * KF + kp] = __float2half_rn(val);
}

__global__ void prep_bias_kernel(const float* __restrict__ bias) {
    int o = threadIdx.x;
    float s = 0.f;
#pragma unroll
    for (int pq = 0; pq < KRr * KAa; pq++) s += bias[pq * Oo + o];
    g_biasK[o] = 2.0f * s;
}

// ---------------------------------------------------------------------------
// Gather + FFT -> X-hat fp16 (unchanged from R8)
// ---------------------------------------------------------------------------
__global__ void gather_fft_kernel(const float* __restrict__ bary) {
    const int warp = blockIdx.x * 8 + (threadIdx.x >> 5);
    const int lane = threadIdx.x & 31;
    const int grp  = lane >> 3;
    const int sub  = lane & 7;
    const int m = warp * 4 + grp;
    if (m >= Mdim) return;

    const int b = m / Nn;
    const int n = m - b * Nn;
    const uint2*  sb = (const uint2*)(g_Sh + (size_t)b * (Nn * Cc));
    const float2* bm = (const float2*)(bary + (size_t)(b * Nn + n) * 240);
    uint2* xrow = (uint2*)(g_Xh + (size_t)m * Kdim);

#pragma unroll
    for (int p = 0; p < KRr; p++) {
        float acc[8][4];
#pragma unroll
        for (int q = 0; q < 8; q++) {
            const float2* bb = bm + (p * 8 + q) * 3;
            float a0 = 0.f, a1 = 0.f, a2 = 0.f, a3 = 0.f;
#pragma unroll
            for (int v = 0; v < 3; v++) {
                float2 iw = bb[v];
                int idx = (int)iw.x;
                uint2 s = sb[idx * 8 + sub];
                float2 f0 = __half22float2(*(const __half2*)&s.x);
                float2 f1 = __half22float2(*(const __half2*)&s.y);
                a0 = fmaf(iw.y, f0.x, a0);
                a1 = fmaf(iw.y, f0.y, a1);
                a2 = fmaf(iw.y, f1.x, a2);
                a3 = fmaf(iw.y, f1.y, a3);
            }
            acc[q][0] = a0; acc[q][1] = a1; acc[q][2] = a2; acc[q][3] = a3;
        }
        float o[4][8];
#pragma unroll
        for (int j = 0; j < 4; j++) {
            float in[8];
#pragma unroll
            for (int q = 0; q < 8; q++) in[q] = acc[q][j];
            fft8(in, o[j]);
        }
#pragma unroll
        for (int comp = 0; comp < 8; comp++) {
            __half2 h0 = __halves2half2(__float2half_rn(o[0][comp]),
                                        __float2half_rn(o[1][comp]));
            __half2 h1 = __halves2half2(__float2half_rn(o[2][comp]),
                                        __float2half_rn(o[3][comp]));
            uint2 v;
            v.x = *(const uint32_t*)&h0;
            v.y = *(const uint32_t*)&h1;
            xrow[comp * 40 + p * 8 + sub] = v;
        }
    }
}

// ---------------------------------------------------------------------------
// FUSED GEMM + combine. One CTA per 128-m tile. 20 chunks = 4 freq blocks x 5.
// Per block g: acc zeroed at chunk g*5, dumped as fp16 to SMEM Y at g*5+4.
// Then in-kernel inverse twiddle + bias -> out.
// ---------------------------------------------------------------------------
__global__ void __launch_bounds__(256, 1)
gemm_fused_kernel(float* __restrict__ out) {
    extern __shared__ __align__(1024) char smem[];
    const uint32_t sb0 = smem_u32(smem);
    const uint32_t ysm = sb0 + YSM_OFF;
    const int tid  = threadIdx.x;
    const int wid  = tid >> 5;
    const int lane = tid & 31;
    const int wm = wid & 3;
    const int wn = wid >> 2;

    const int m0 = blockIdx.x * 128;

    const int l_row = tid >> 3;
    const int l_seg = tid & 7;
    const uint32_t l_doff = l_row * 128 + ((l_seg ^ (l_row & 7)) << 4);
    const __half* aptr = g_Xh + (size_t)(m0 + l_row) * Kdim + l_seg * 8;
    const __half* bptr = g_Wb + (size_t)l_row * KF + l_seg * 8;

    auto load_stage = [&](int t) {
        const int g = t / 5, c = t - 5 * g;
        const uint32_t sb = sb0 + (t % NSTAGE) * STAGE_BYTES;
        const __half* a = aptr + t * KCHUNK;                 // X row is contiguous
        const __half* b = bptr + (size_t)g * (NF * KF) + c * KCHUNK;
#pragma unroll
        for (int i = 0; i < 4; i++) {
            uint32_t d = sb + l_doff + i * (32 * 128);
            cp16(d,         a + (size_t)(i * 32) * Kdim);
            cp16(d + B_OFF, b + (size_t)(i * 32) * KF);
        }
        asm volatile("cp.async.commit_group;" ::: "memory");
    };

    const int sel = lane >> 4;
    uint32_t a_base[2], b_base[4];
#pragma unroll
    for (int mt = 0; mt < 2; mt++) {
        int r = wm * 32 + (lane & 15) + mt * 16;
        a_base[mt] = r * 128 + (((sel ^ r) & 7) << 4);
    }
#pragma unroll
    for (int bt = 0; bt < 4; bt++) {
        int r = wn * 64 + (lane & 15) + bt * 16;
        b_base[bt] = B_OFF + r * 128 + (((sel ^ r) & 7) << 4);
    }

    float acc[2][8][4];
    const int ob = (lane & 3) * 2;

    load_stage(0);
    load_stage(1);

    for (int t = 0; t < NCHUNK_T; t++) {
        if (t + 1 < NCHUNK_T) asm volatile("cp.async.wait_group 1;" ::: "memory");
        else                  asm volatile("cp.async.wait_group 0;" ::: "memory");
        __syncthreads();
        if (t + 2 < NCHUNK_T) load_stage(t + 2);

        const int g = t / 5, c = t - 5 * g;
        if (c == 0) {
#pragma unroll
            for (int mt = 0; mt < 2; mt++)
#pragma unroll
                for (int nt = 0; nt < 8; nt++)
#pragma unroll
                    for (int i = 0; i < 4; i++) acc[mt][nt][i] = 0.f;
        }

        const uint32_t sb = sb0 + (t % NSTAGE) * STAGE_BYTES;

#pragma unroll
        for (int ks = 0; ks < 4; ks++) {
            const uint32_t xv = ks << 5;
            uint32_t ah[2][4];
#pragma unroll
            for (int mt = 0; mt < 2; mt++)
                ldsm_x4((sb + a_base[mt]) ^ xv, ah[mt][0], ah[mt][1], ah[mt][2], ah[mt][3]);
            uint32_t bh[8][2];
#pragma unroll
            for (int bt = 0; bt < 4; bt++) {
                uint32_t r0, r1, r2, r3;
                ldsm_x4((sb + b_base[bt]) ^ xv, r0, r1, r2, r3);
                bh[2 * bt][0] = r0; bh[2 * bt][1] = r2;
                bh[2 * bt + 1][0] = r1; bh[2 * bt + 1][1] = r3;
            }
#pragma unroll
            for (int mt = 0; mt < 2; mt++)
#pragma unroll
                for (int nt = 0; nt < 8; nt++)
                    mma16816(acc[mt][nt], ah[mt], bh[nt][0], bh[nt][1]);
        }

        if (c == 4) {
            // dump this block's acc to SMEM Y as fp16 (warp-private rows, no sync)
#pragma unroll
            for (int mt = 0; mt < 2; mt++) {
#pragma unroll
                for (int half = 0; half < 2; half++) {
                    int row = wm * 32 + mt * 16 + (lane >> 2) + half * 8;   // local m
                    uint32_t yp = ysm + (uint32_t)(row * 512 + g * NF + wn * 64 + ob) * 2;
#pragma unroll
                    for (int nt = 0; nt < 8; nt++) {
                        __half2 hv = __floats2half2_rn(acc[mt][nt][half * 2 + 0],
                                                       acc[mt][nt][half * 2 + 1]);
                        asm volatile("st.shared.b32 [%0], %1;"
                                     :: "r"(yp + nt * 16), "r"(*(const uint32_t*)&hv));
                    }
                }
            }
        }
    }

    __syncthreads();

    // ---- in-kernel combine: warp handles 16 local m rows, lane = o-pair
    const float bx = g_biasK[2 * lane];
    const float by = g_biasK[2 * lane + 1];

    const float C1[8] = {1.f, SQH, 0.f, -SQH, -1.f, -SQH, 0.f, SQH};
    const float S1[8] = {0.f, SQH, 1.f, SQH, 0.f, -SQH, -1.f, -SQH};
    const float C2[8] = {1.f, 0.f, -1.f, 0.f, 1.f, 0.f, -1.f, 0.f};
    const float S2[8] = {0.f, 1.f, 0.f, -1.f, 0.f, 1.f, 0.f, -1.f};
    const float C3[8] = {1.f, -SQH, 0.f, SQH, -1.f, SQH, 0.f, -SQH};
    const float S3[8] = {0.f, SQH, -1.f, SQH, 0.f, -SQH, 1.f, -SQH};

    for (int mm = 0; mm < 16; mm++) {
        const int ml = wid * 16 + mm;
        const int m = m0 + ml;
        if (m >= Mdim) continue;

        float2 Yc[8];
#pragma unroll
        for (int comp = 0; comp < 8; comp++) {
            uint32_t v;
            asm volatile("ld.shared.b32 %0, [%1];" : "=r"(v)
                         : "r"(ysm + (uint32_t)(ml * 512 + comp * 64 + 2 * lane) * 2));
            Yc[comp] = __half22float2(*(const __half2*)&v);
        }
        const float2 Z0 = Yc[0], Z4 = Yc[1];
        const float2 R1 = Yc[2], I1 = Yc[3];
        const float2 R2 = Yc[4], I2 = Yc[5];
        const float2 R3 = Yc[6], I3 = Yc[7];

        const int b = m / Nn;
        const int n = m - b * Nn;
        float* op = out + (size_t)b * ((size_t)KAa * Nn * Oo) + (size_t)n * Oo + 2 * lane;

#pragma unroll
        for (int r = 0; r < 8; r++) {
            float sg = (r & 1) ? -1.f : 1.f;
            float2 v;
            v.x = 0.125f * (Z0.x + sg * Z4.x)
                + 0.25f * (C1[r] * R1.x - S1[r] * I1.x
                         + C2[r] * R2.x - S2[r] * I2.x
                         + C3[r] * R3.x - S3[r] * I3.x) + bx;
            v.y = 0.125f * (Z0.y + sg * Z4.y)
                + 0.25f * (C1[r] * R1.y - S1[r] * I1.y
                         + C2[r] * R2.y - S2[r] * I2.y
                         + C3[r] * R3.y - S3[r] * I3.y) + by;
            *(float2*)&op[(size_t)r * (Nn * Oo)] = v;
        }
    }
}

// ---------------------------------------------------------------------------
extern "C" void kernel_launch(void* const* d_in, const int* in_sizes, int n_in,
                              void* d_out, int out_size) {
    const float* signal  = (const float*)d_in[0];
    const float* bary    = (const float*)d_in[1];
    const float* kernels = (const float*)d_in[2];
    const float* bias    = (const float*)d_in[3];
    float* out = (float*)d_out;

    conv_signal_kernel<<<(4 * Nn * Cc / 4 + 255) / 256, 256>>>(signal);
    prep_wb_kernel<<<NBLK * NF, KF>>>(kernels);
    prep_bias_kernel<<<1, Oo>>>(bias);

    gather_fft_kernel<<<Mdim / 32, 256>>>(bary);

    {
        static int smem_set = 0;
        if (!smem_set) {
            cudaFuncSetAttribute(gemm_fused_kernel,
                                 cudaFuncAttributeMaxDynamicSharedMemorySize, FUSED_SMEM);
            smem_set = 1;
        }
        gemm_fused_kernel<<<Mpad / 128, 256, FUSED_SMEM>>>(out);
    }
}

// round 10
// speedup vs baseline: 1.1636x; 1.1636x over previous
#include <cuda_runtime.h>
#include <cuda_fp16.h>
#include <cstdint>

// ---------------- problem constants ----------------
#define Nn   10000
#define KRr  5
#define KAa  8
#define Cc   32
#define Oo   64

#define Mdim 40000            // B*N
#define Kdim 1280             // KR*KA*C  (X-hat row width)
#define Mpad 40064            // 313 * 128

// ---------------- frequency-block GEMM tiling ----------------
#define KF   320                   // K per freq block
#define NF   128                   // N per freq block
#define NBLK 4                     // {f0|f4}, f1, f2, f3
#define KCHUNK 64                  // fp16 per K chunk (128 B per row)
#define NCHUNK_F (KF / KCHUNK)     // 5
#define B_OFF 16384
#define STAGE_BYTES 32768
#define NSTAGE 3
#define GEMM_SMEM (NSTAGE * STAGE_BYTES)   // 98304 -> 2 CTAs/SM

#define SQH 0.70710678118654752f

// ---------------- device scratch ----------------
__device__ __half g_Xh[(size_t)Mpad * Kdim];        // X-hat fp16 (freq layout)
__device__ __half g_Wb[(size_t)NBLK * NF * KF];     // W-hat blocks [4][128][320]
__device__ __half g_Sh[(size_t)4 * Nn * Cc];        // signal fp16
__device__ __half g_Yh[(size_t)Mpad * 512];         // freq-domain GEMM output (fp16)
__device__ float  g_biasK[Oo];

// ---------------- helpers ----------------
__device__ __forceinline__ uint32_t smem_u32(const void* p) {
    uint32_t a;
    asm("{ .reg .u64 t; cvta.to.shared.u64 t, %1; cvt.u32.u64 %0, t; }" : "=r"(a) : "l"(p));
    return a;
}
__device__ __forceinline__ void cp16(uint32_t dst, const void* src) {
    asm volatile("cp.async.cg.shared.global [%0], [%1], 16;" :: "r"(dst), "l"(src));
}
__device__ __forceinline__ void ldsm_x4(uint32_t addr, uint32_t& r0, uint32_t& r1,
                                        uint32_t& r2, uint32_t& r3) {
    asm volatile("ldmatrix.sync.aligned.m8n8.x4.shared.b16 {%0,%1,%2,%3}, [%4];"
                 : "=r"(r0), "=r"(r1), "=r"(r2), "=r"(r3) : "r"(addr));
}
__device__ __forceinline__ void mma16816(float* c, const uint32_t* a,
                                         uint32_t b0, uint32_t b1) {
    asm volatile(
        "mma.sync.aligned.m16n8k16.row.col.f32.f16.f16.f32 "
        "{%0,%1,%2,%3}, {%4,%5,%6,%7}, {%8,%9}, {%0,%1,%2,%3};"
        : "+f"(c[0]), "+f"(c[1]), "+f"(c[2]), "+f"(c[3])
        : "r"(a[0]), "r"(a[1]), "r"(a[2]), "r"(a[3]), "r"(b0), "r"(b1));
}

// 8-point real DFT: x[0..7] -> {X0, X4, Re1, Im1, Re2, Im2, Re3, Im3}
__device__ __forceinline__ void fft8(const float* x, float* o) {
    float p04 = x[0] + x[4], m04 = x[0] - x[4];
    float p26 = x[2] + x[6], m26 = x[2] - x[6];
    float pbd = x[1] + x[3], pfh = x[5] + x[7];
    float mbd = x[1] - x[3], mfh = x[5] - x[7];
    float sodd = pbd + pfh;
    float B1 = mbd - mfh;
    float B2 = pfh - pbd;
    o[0] = p04 + p26 + sodd;
    o[1] = p04 + p26 - sodd;
    o[2] = m04 + SQH * B1;
    o[3] = -m26 + SQH * B2;
    o[4] = p04 - p26;
    o[5] = -(mbd + mfh);
    o[6] = m04 - SQH * B1;
    o[7] = m26 + SQH * B2;
}

// ---------------------------------------------------------------------------
__global__ void conv_signal_kernel(const float* __restrict__ signal) {
    int i = blockIdx.x * blockDim.x + threadIdx.x;
    if (i >= (4 * Nn * Cc) / 4) return;
    float4 v = ((const float4*)signal)[i];
    __half2 h0 = __halves2half2(__float2half_rn(v.x), __float2half_rn(v.y));
    __half2 h1 = __halves2half2(__float2half_rn(v.z), __float2half_rn(v.w));
    ((__half2*)g_Sh)[2 * i]     = h0;
    ((__half2*)g_Sh)[2 * i + 1] = h1;
}

// ---------------------------------------------------------------------------
// Prep W-hat blocks
// ---------------------------------------------------------------------------
__global__ void prep_wb_kernel(const float* __restrict__ kernels) {
    const int row = blockIdx.x;            // 0..511
    const int g = row >> 7;
    const int np = row & 127;
    const int h = np >> 6, o = np & 63;
    const int kp = threadIdx.x;            // 0..319
    const int half = (kp >= 160) ? 1 : 0;
    const int kk = kp - 160 * half;
    const int p = kk >> 5, c = kk & 31;

    float wsum[8];
#pragma unroll
    for (int q = 0; q < 8; q++) {
        int base = p * 16384 + q * 2048 + o * 32 + c;
        wsum[q] = kernels[base] + kernels[81920 + base];
    }

    float val = 0.f;
    if (g == 0) {
        if (h == 0 && half == 0) {
#pragma unroll
            for (int q = 0; q < 8; q++) val += wsum[q];
        } else if (h == 1 && half == 1) {
#pragma unroll
            for (int q = 0; q < 8; q++) val += (q & 1) ? -wsum[q] : wsum[q];
        }
    } else {
        const float ct[8] = {1.f, SQH, 0.f, -SQH, -1.f, -SQH, 0.f, SQH};
        const float st[8] = {0.f, SQH, 1.f, SQH, 0.f, -SQH, -1.f, -SQH};
        float Wr = 0.f, Wi = 0.f;
#pragma unroll
        for (int q = 0; q < 8; q++) {
            int i = (g * q) & 7;
            Wr += wsum[q] * ct[i];
            Wi -= wsum[q] * st[i];
        }
        if (h == 0) val = half ? Wi : Wr;
        else        val = half ? -Wr : Wi;
    }
    g_Wb[(size_t)row * KF + kp] = __float2half_rn(val);
}

__global__ void prep_bias_kernel(const float* __restrict__ bias) {
    int o = threadIdx.x;
    float s = 0.f;
#pragma unroll
    for (int pq = 0; pq < KRr * KAa; pq++) s += bias[pq * Oo + o];
    g_biasK[o] = 2.0f * s;
}

// ---------------------------------------------------------------------------
// Gather + FFT -> X-hat fp16 (proven R8 version)
// ---------------------------------------------------------------------------
__global__ void gather_fft_kernel(const float* __restrict__ bary) {
    const int warp = blockIdx.x * 8 + (threadIdx.x >> 5);
    const int lane = threadIdx.x & 31;
    const int grp  = lane >> 3;
    const int sub  = lane & 7;
    const int m = warp * 4 + grp;
    if (m >= Mdim) return;

    const int b = m / Nn;
    const int n = m - b * Nn;
    const uint2*  sb = (const uint2*)(g_Sh + (size_t)b * (Nn * Cc));
    const float2* bm = (const float2*)(bary + (size_t)(b * Nn + n) * 240);
    uint2* xrow = (uint2*)(g_Xh + (size_t)m * Kdim);

#pragma unroll
    for (int p = 0; p < KRr; p++) {
        float acc[8][4];
#pragma unroll
        for (int q = 0; q < 8; q++) {
            const float2* bb = bm + (p * 8 + q) * 3;
            float a0 = 0.f, a1 = 0.f, a2 = 0.f, a3 = 0.f;
#pragma unroll
            for (int v = 0; v < 3; v++) {
                float2 iw = bb[v];
                int idx = (int)iw.x;
                uint2 s = sb[idx * 8 + sub];
                float2 f0 = __half22float2(*(const __half2*)&s.x);
                float2 f1 = __half22float2(*(const __half2*)&s.y);
                a0 = fmaf(iw.y, f0.x, a0);
                a1 = fmaf(iw.y, f0.y, a1);
                a2 = fmaf(iw.y, f1.x, a2);
                a3 = fmaf(iw.y, f1.y, a3);
            }
            acc[q][0] = a0; acc[q][1] = a1; acc[q][2] = a2; acc[q][3] = a3;
        }
        float o[4][8];
#pragma unroll
        for (int j = 0; j < 4; j++) {
            float in[8];
#pragma unroll
            for (int q = 0; q < 8; q++) in[q] = acc[q][j];
            fft8(in, o[j]);
        }
#pragma unroll
        for (int comp = 0; comp < 8; comp++) {
            __half2 h0 = __halves2half2(__float2half_rn(o[0][comp]),
                                        __float2half_rn(o[1][comp]));
            __half2 h1 = __halves2half2(__float2half_rn(o[2][comp]),
                                        __float2half_rn(o[3][comp]));
            uint2 v;
            v.x = *(const uint32_t*)&h0;
            v.y = *(const uint32_t*)&h1;
            xrow[comp * 40 + p * 8 + sub] = v;
        }
    }
}

// ---------------------------------------------------------------------------
// HMMA GEMM per freq block (R8 structure); epilogue writes Y as fp16.
// ---------------------------------------------------------------------------
__global__ void __launch_bounds__(256, 2)
gemm_mma_kernel() {
    extern __shared__ __align__(1024) char smem[];
    const uint32_t sb0 = smem_u32(smem);
    const int tid  = threadIdx.x;
    const int wid  = tid >> 5;
    const int lane = tid & 31;
    const int wm = wid & 3;
    const int wn = wid >> 2;

    const int g  = blockIdx.x;
    const int m0 = blockIdx.y * 128;

    const int l_row = tid >> 3;
    const int l_seg = tid & 7;
    const uint32_t l_doff = l_row * 128 + ((l_seg ^ (l_row & 7)) << 4);
    const __half* aptr = g_Xh + (size_t)(m0 + l_row) * Kdim + g * KF + l_seg * 8;
    const __half* bptr = g_Wb + (size_t)(g * NF + l_row) * KF + l_seg * 8;

    auto load_stage = [&](int c) {
        const uint32_t sb = sb0 + (c % NSTAGE) * STAGE_BYTES;
        const __half* a = aptr + c * KCHUNK;
        const __half* b = bptr + c * KCHUNK;
#pragma unroll
        for (int i = 0; i < 4; i++) {
            uint32_t d = sb + l_doff + i * (32 * 128);
            cp16(d,         a + (size_t)(i * 32) * Kdim);
            cp16(d + B_OFF, b + (size_t)(i * 32) * KF);
        }
        asm volatile("cp.async.commit_group;" ::: "memory");
    };

    float acc[2][8][4];
#pragma unroll
    for (int mt = 0; mt < 2; mt++)
#pragma unroll
        for (int nt = 0; nt < 8; nt++)
#pragma unroll
            for (int i = 0; i < 4; i++) acc[mt][nt][i] = 0.f;

    const int sel = lane >> 4;
    uint32_t a_base[2], b_base[4];
#pragma unroll
    for (int mt = 0; mt < 2; mt++) {
        int r = wm * 32 + (lane & 15) + mt * 16;
        a_base[mt] = r * 128 + (((sel ^ r) & 7) << 4);
    }
#pragma unroll
    for (int bt = 0; bt < 4; bt++) {
        int r = wn * 64 + (lane & 15) + bt * 16;
        b_base[bt] = B_OFF + r * 128 + (((sel ^ r) & 7) << 4);
    }

    load_stage(0);
    load_stage(1);

    for (int c = 0; c < NCHUNK_F; c++) {
        if (c + 1 < NCHUNK_F) asm volatile("cp.async.wait_group 1;" ::: "memory");
        else                  asm volatile("cp.async.wait_group 0;" ::: "memory");
        __syncthreads();
        if (c + 2 < NCHUNK_F) load_stage(c + 2);

        const uint32_t sb = sb0 + (c % NSTAGE) * STAGE_BYTES;

#pragma unroll
        for (int ks = 0; ks < 4; ks++) {
            const uint32_t xv = ks << 5;
            uint32_t ah[2][4];
#pragma unroll
            for (int mt = 0; mt < 2; mt++)
                ldsm_x4((sb + a_base[mt]) ^ xv, ah[mt][0], ah[mt][1], ah[mt][2], ah[mt][3]);
            uint32_t bh[8][2];
#pragma unroll
            for (int bt = 0; bt < 4; bt++) {
                uint32_t r0, r1, r2, r3;
                ldsm_x4((sb + b_base[bt]) ^ xv, r0, r1, r2, r3);
                bh[2 * bt][0] = r0; bh[2 * bt][1] = r2;
                bh[2 * bt + 1][0] = r1; bh[2 * bt + 1][1] = r3;
            }
#pragma unroll
            for (int mt = 0; mt < 2; mt++)
#pragma unroll
                for (int nt = 0; nt < 8; nt++)
                    mma16816(acc[mt][nt], ah[mt], bh[nt][0], bh[nt][1]);
        }
    }

    // epilogue: write Y block as fp16
    const int ob = (lane & 3) * 2;
#pragma unroll
    for (int mt = 0; mt < 2; mt++) {
#pragma unroll
        for (int half = 0; half < 2; half++) {
            int m = m0 + wm * 32 + mt * 16 + (lane >> 2) + half * 8;
            __half* yp = g_Yh + (size_t)m * 512 + g * NF + wn * 64;
#pragma unroll
            for (int nt = 0; nt < 8; nt++) {
                __half2 hv = __floats2half2_rn(acc[mt][nt][half * 2 + 0],
                                               acc[mt][nt][half * 2 + 1]);
                *(__half2*)&yp[nt * 8 + ob] = hv;
            }
        }
    }
}

// ---------------------------------------------------------------------------
// Combine: inverse twiddle + bias, reading fp16 Y.
// ---------------------------------------------------------------------------
__global__ void combine_kernel(float* __restrict__ out) {
    const int m = blockIdx.x * 8 + (threadIdx.x >> 5);
    if (m >= Mdim) return;
    const int lane = threadIdx.x & 31;

    const __half2* y2 = (const __half2*)(g_Yh + (size_t)m * 512);
    float2 Z0 = __half22float2(y2[lane]);
    float2 Z4 = __half22float2(y2[32 + lane]);
    float2 R1 = __half22float2(y2[64 + lane]);
    float2 I1 = __half22float2(y2[96 + lane]);
    float2 R2 = __half22float2(y2[128 + lane]);
    float2 I2 = __half22float2(y2[160 + lane]);
    float2 R3 = __half22float2(y2[192 + lane]);
    float2 I3 = __half22float2(y2[224 + lane]);

    const float bx = g_biasK[2 * lane];
    const float by = g_biasK[2 * lane + 1];

    const int b = m / Nn;
    const int n = m - b * Nn;
    float* op = out + (size_t)b * ((size_t)KAa * Nn * Oo) + (size_t)n * Oo + 2 * lane;

    const float C1[8] = {1.f, SQH, 0.f, -SQH, -1.f, -SQH, 0.f, SQH};
    const float S1[8] = {0.f, SQH, 1.f, SQH, 0.f, -SQH, -1.f, -SQH};
    const float C2[8] = {1.f, 0.f, -1.f, 0.f, 1.f, 0.f, -1.f, 0.f};
    const float S2[8] = {0.f, 1.f, 0.f, -1.f, 0.f, 1.f, 0.f, -1.f};
    const float C3[8] = {1.f, -SQH, 0.f, SQH, -1.f, SQH, 0.f, -SQH};
    const float S3[8] = {0.f, SQH, -1.f, SQH, 0.f, -SQH, 1.f, -SQH};

#pragma unroll
    for (int r = 0; r < 8; r++) {
        float sg = (r & 1) ? -1.f : 1.f;
        float2 v;
        v.x = 0.125f * (Z0.x + sg * Z4.x)
            + 0.25f * (C1[r] * R1.x - S1[r] * I1.x
                     + C2[r] * R2.x - S2[r] * I2.x
                     + C3[r] * R3.x - S3[r] * I3.x) + bx;
        v.y = 0.125f * (Z0.y + sg * Z4.y)
            + 0.25f * (C1[r] * R1.y - S1[r] * I1.y
                     + C2[r] * R2.y - S2[r] * I2.y
                     + C3[r] * R3.y - S3[r] * I3.y) + by;
        *(float2*)&op[(size_t)r * (Nn * Oo)] = v;
    }
}

// ---------------------------------------------------------------------------
extern "C" void kernel_launch(void* const* d_in, const int* in_sizes, int n_in,
                              void* d_out, int out_size) {
    const float* signal  = (const float*)d_in[0];
    const float* bary    = (const float*)d_in[1];
    const float* kernels = (const float*)d_in[2];
    const float* bias    = (const float*)d_in[3];
    float* out = (float*)d_out;

    conv_signal_kernel<<<(4 * Nn * Cc / 4 + 255) / 256, 256>>>(signal);
    prep_wb_kernel<<<NBLK * NF, KF>>>(kernels);
    prep_bias_kernel<<<1, Oo>>>(bias);

    gather_fft_kernel<<<Mdim / 32, 256>>>(bary);

    {
        static int smem_set = 0;
        if (!smem_set) {
            cudaFuncSetAttribute(gemm_mma_kernel,
                                 cudaFuncAttributeMaxDynamicSharedMemorySize, GEMM_SMEM);
            smem_set = 1;
        }
        dim3 grid(NBLK, Mpad / 128);   // (4, 313)
        gemm_mma_kernel<<<grid, 256, GEMM_SMEM>>>();
    }

    combine_kernel<<<Mdim / 8, 256>>>(out);
}

// round 11
// speedup vs baseline: 1.2751x; 1.0958x over previous
#include <cuda_runtime.h>
#include <cuda_fp16.h>
#include <cstdint>

// ---------------- problem constants ----------------
#define Nn   10000
#define KRr  5
#define KAa  8
#define Cc   32
#define Oo   64

#define Mdim 40000            // B*N
#define Kdim 1280             // KR*KA*C  (X-hat row width)
#define Mpad 40064            // 313 * 128

// ---------------- frequency-block GEMM tiling ----------------
#define KF   320                   // K per freq block
#define NF   128                   // N per freq block
#define NBLK 4                     // {f0|f4}, f1, f2, f3
#define KCHUNK 64                  // fp16 per K chunk (128 B per row)
#define NCHUNK_F (KF / KCHUNK)     // 5
#define B_OFF 16384
#define STAGE_BYTES 32768
#define NSTAGE 3
#define GEMM_SMEM (NSTAGE * STAGE_BYTES)   // 98304 -> 2 CTAs/SM

#define SQH 0.70710678118654752f

// ---------------- device scratch ----------------
__device__ __half g_Xh[(size_t)Mpad * Kdim];        // X-hat fp16 (freq layout)
__device__ __half g_Wb[(size_t)NBLK * NF * KF];     // W-hat blocks [4][128][320]
__device__ __half g_Sh[(size_t)4 * Nn * Cc];        // signal fp16
__device__ __half g_Yh[(size_t)Mpad * 512];         // freq-domain GEMM output (fp16)
__device__ float  g_biasK[Oo];

// ---------------- helpers ----------------
__device__ __forceinline__ uint32_t smem_u32(const void* p) {
    uint32_t a;
    asm("{ .reg .u64 t; cvta.to.shared.u64 t, %1; cvt.u32.u64 %0, t; }" : "=r"(a) : "l"(p));
    return a;
}
__device__ __forceinline__ void cp16(uint32_t dst, const void* src) {
    asm volatile("cp.async.cg.shared.global [%0], [%1], 16;" :: "r"(dst), "l"(src));
}
__device__ __forceinline__ void ldsm_x4(uint32_t addr, uint32_t& r0, uint32_t& r1,
                                        uint32_t& r2, uint32_t& r3) {
    asm volatile("ldmatrix.sync.aligned.m8n8.x4.shared.b16 {%0,%1,%2,%3}, [%4];"
                 : "=r"(r0), "=r"(r1), "=r"(r2), "=r"(r3) : "r"(addr));
}
__device__ __forceinline__ void mma16816(float* c, const uint32_t* a,
                                         uint32_t b0, uint32_t b1) {
    asm volatile(
        "mma.sync.aligned.m16n8k16.row.col.f32.f16.f16.f32 "
        "{%0,%1,%2,%3}, {%4,%5,%6,%7}, {%8,%9}, {%0,%1,%2,%3};"
        : "+f"(c[0]), "+f"(c[1]), "+f"(c[2]), "+f"(c[3])
        : "r"(a[0]), "r"(a[1]), "r"(a[2]), "r"(a[3]), "r"(b0), "r"(b1));
}

// 8-point real DFT: x[0..7] -> {X0, X4, Re1, Im1, Re2, Im2, Re3, Im3}
__device__ __forceinline__ void fft8(const float* x, float* o) {
    float p04 = x[0] + x[4], m04 = x[0] - x[4];
    float p26 = x[2] + x[6], m26 = x[2] - x[6];
    float pbd = x[1] + x[3], pfh = x[5] + x[7];
    float mbd = x[1] - x[3], mfh = x[5] - x[7];
    float sodd = pbd + pfh;
    float B1 = mbd - mfh;
    float B2 = pfh - pbd;
    o[0] = p04 + p26 + sodd;
    o[1] = p04 + p26 - sodd;
    o[2] = m04 + SQH * B1;
    o[3] = -m26 + SQH * B2;
    o[4] = p04 - p26;
    o[5] = -(mbd + mfh);
    o[6] = m04 - SQH * B1;
    o[7] = m26 + SQH * B2;
}

// ---------------------------------------------------------------------------
__global__ void conv_signal_kernel(const float* __restrict__ signal) {
    int i = blockIdx.x * blockDim.x + threadIdx.x;
    if (i >= (4 * Nn * Cc) / 4) return;
    float4 v = ((const float4*)signal)[i];
    __half2 h0 = __halves2half2(__float2half_rn(v.x), __float2half_rn(v.y));
    __half2 h1 = __halves2half2(__float2half_rn(v.z), __float2half_rn(v.w));
    ((__half2*)g_Sh)[2 * i]     = h0;
    ((__half2*)g_Sh)[2 * i + 1] = h1;
}

// ---------------------------------------------------------------------------
// Prep W-hat blocks
// ---------------------------------------------------------------------------
__global__ void prep_wb_kernel(const float* __restrict__ kernels) {
    const int row = blockIdx.x;            // 0..511
    const int g = row >> 7;
    const int np = row & 127;
    const int h = np >> 6, o = np & 63;
    const int kp = threadIdx.x;            // 0..319
    const int half = (kp >= 160) ? 1 : 0;
    const int kk = kp - 160 * half;
    const int p = kk >> 5, c = kk & 31;

    float wsum[8];
#pragma unroll
    for (int q = 0; q < 8; q++) {
        int base = p * 16384 + q * 2048 + o * 32 + c;
        wsum[q] = kernels[base] + kernels[81920 + base];
    }

    float val = 0.f;
    if (g == 0) {
        if (h == 0 && half == 0) {
#pragma unroll
            for (int q = 0; q < 8; q++) val += wsum[q];
        } else if (h == 1 && half == 1) {
#pragma unroll
            for (int q = 0; q < 8; q++) val += (q & 1) ? -wsum[q] : wsum[q];
        }
    } else {
        const float ct[8] = {1.f, SQH, 0.f, -SQH, -1.f, -SQH, 0.f, SQH};
        const float st[8] = {0.f, SQH, 1.f, SQH, 0.f, -SQH, -1.f, -SQH};
        float Wr = 0.f, Wi = 0.f;
#pragma unroll
        for (int q = 0; q < 8; q++) {
            int i = (g * q) & 7;
            Wr += wsum[q] * ct[i];
            Wi -= wsum[q] * st[i];
        }
        if (h == 0) val = half ? Wi : Wr;
        else        val = half ? -Wr : Wi;
    }
    g_Wb[(size_t)row * KF + kp] = __float2half_rn(val);
}

__global__ void prep_bias_kernel(const float* __restrict__ bias) {
    int o = threadIdx.x;
    float s = 0.f;
#pragma unroll
    for (int pq = 0; pq < KRr * KAa; pq++) s += bias[pq * Oo + o];
    g_biasK[o] = 2.0f * s;
}

// ---------------------------------------------------------------------------
// Gather + FFT -> X-hat fp16, with bary staged in SMEM.
// CTA covers 32 contiguous m (8 warps x 4 m). Bary block for those 32 m is
// one contiguous 30720B gmem region -> coalesced float4 bulk load into SMEM,
// then inner loop reads (idx,w) via broadcast ld.shared.v2.
// ---------------------------------------------------------------------------
__global__ void __launch_bounds__(256)
gather_fft_kernel(const float* __restrict__ bary) {
    __shared__ __align__(16) float sbary[32 * 240];   // 30720 B

    const int tid  = threadIdx.x;
    const int wid  = tid >> 5;
    const int lane = tid & 31;
    const int grp  = lane >> 3;
    const int sub  = lane & 7;

    const int m0blk = blockIdx.x * 32;
    const int ml = wid * 4 + grp;          // local m in [0,32)
    const int m  = m0blk + ml;

    // stage bary block (perfectly coalesced)
    {
        const float4* src = (const float4*)(bary + (size_t)m0blk * 240);
        float4* dst = (float4*)sbary;
#pragma unroll
        for (int i = 0; i < 1920 / 256; i++)
            dst[tid + i * 256] = src[tid + i * 256];
        // 1920 = 32*240/4; 1920/256 = 7.5 -> handle remainder
        if (tid < 1920 - (1920 / 256) * 256)
            dst[tid + (1920 / 256) * 256] = src[tid + (1920 / 256) * 256];
    }
    __syncthreads();

    const int b = m / Nn;
    const int n_unused = 0; (void)n_unused;
    const uint2* sb = (const uint2*)(g_Sh + (size_t)b * (Nn * Cc));
    const float2* bm = (const float2*)(sbary + ml * 240);
    uint2* xrow = (uint2*)(g_Xh + (size_t)m * Kdim);

#pragma unroll
    for (int p = 0; p < KRr; p++) {
        float acc[8][4];
#pragma unroll
        for (int q = 0; q < 8; q++) {
            const float2* bb = bm + (p * 8 + q) * 3;
            float a0 = 0.f, a1 = 0.f, a2 = 0.f, a3 = 0.f;
#pragma unroll
            for (int v = 0; v < 3; v++) {
                float2 iw = bb[v];                 // ld.shared.v2 broadcast
                int idx = (int)iw.x;
                uint2 s = sb[idx * 8 + sub];
                float2 f0 = __half22float2(*(const __half2*)&s.x);
                float2 f1 = __half22float2(*(const __half2*)&s.y);
                a0 = fmaf(iw.y, f0.x, a0);
                a1 = fmaf(iw.y, f0.y, a1);
                a2 = fmaf(iw.y, f1.x, a2);
                a3 = fmaf(iw.y, f1.y, a3);
            }
            acc[q][0] = a0; acc[q][1] = a1; acc[q][2] = a2; acc[q][3] = a3;
        }
        float o[4][8];
#pragma unroll
        for (int j = 0; j < 4; j++) {
            float in[8];
#pragma unroll
            for (int q = 0; q < 8; q++) in[q] = acc[q][j];
            fft8(in, o[j]);
        }
#pragma unroll
        for (int comp = 0; comp < 8; comp++) {
            __half2 h0 = __halves2half2(__float2half_rn(o[0][comp]),
                                        __float2half_rn(o[1][comp]));
            __half2 h1 = __halves2half2(__float2half_rn(o[2][comp]),
                                        __float2half_rn(o[3][comp]));
            uint2 v;
            v.x = *(const uint32_t*)&h0;
            v.y = *(const uint32_t*)&h1;
            xrow[comp * 40 + p * 8 + sub] = v;
        }
    }
}

// ---------------------------------------------------------------------------
// HMMA GEMM per freq block; epilogue writes Y as fp16. (proven R10 version)
// ---------------------------------------------------------------------------
__global__ void __launch_bounds__(256, 2)
gemm_mma_kernel() {
    extern __shared__ __align__(1024) char smem[];
    const uint32_t sb0 = smem_u32(smem);
    const int tid  = threadIdx.x;
    const int wid  = tid >> 5;
    const int lane = tid & 31;
    const int wm = wid & 3;
    const int wn = wid >> 2;

    const int g  = blockIdx.x;
    const int m0 = blockIdx.y * 128;

    const int l_row = tid >> 3;
    const int l_seg = tid & 7;
    const uint32_t l_doff = l_row * 128 + ((l_seg ^ (l_row & 7)) << 4);
    const __half* aptr = g_Xh + (size_t)(m0 + l_row) * Kdim + g * KF + l_seg * 8;
    const __half* bptr = g_Wb + (size_t)(g * NF + l_row) * KF + l_seg * 8;

    auto load_stage = [&](int c) {
        const uint32_t sb = sb0 + (c % NSTAGE) * STAGE_BYTES;
        const __half* a = aptr + c * KCHUNK;
        const __half* b = bptr + c * KCHUNK;
#pragma unroll
        for (int i = 0; i < 4; i++) {
            uint32_t d = sb + l_doff + i * (32 * 128);
            cp16(d,         a + (size_t)(i * 32) * Kdim);
            cp16(d + B_OFF, b + (size_t)(i * 32) * KF);
        }
        asm volatile("cp.async.commit_group;" ::: "memory");
    };

    float acc[2][8][4];
#pragma unroll
    for (int mt = 0; mt < 2; mt++)
#pragma unroll
        for (int nt = 0; nt < 8; nt++)
#pragma unroll
            for (int i = 0; i < 4; i++) acc[mt][nt][i] = 0.f;

    const int sel = lane >> 4;
    uint32_t a_base[2], b_base[4];
#pragma unroll
    for (int mt = 0; mt < 2; mt++) {
        int r = wm * 32 + (lane & 15) + mt * 16;
        a_base[mt] = r * 128 + (((sel ^ r) & 7) << 4);
    }
#pragma unroll
    for (int bt = 0; bt < 4; bt++) {
        int r = wn * 64 + (lane & 15) + bt * 16;
        b_base[bt] = B_OFF + r * 128 + (((sel ^ r) & 7) << 4);
    }

    load_stage(0);
    load_stage(1);

    for (int c = 0; c < NCHUNK_F; c++) {
        if (c + 1 < NCHUNK_F) asm volatile("cp.async.wait_group 1;" ::: "memory");
        else                  asm volatile("cp.async.wait_group 0;" ::: "memory");
        __syncthreads();
        if (c + 2 < NCHUNK_F) load_stage(c + 2);

        const uint32_t sb = sb0 + (c % NSTAGE) * STAGE_BYTES;

#pragma unroll
        for (int ks = 0; ks < 4; ks++) {
            const uint32_t xv = ks << 5;
            uint32_t ah[2][4];
#pragma unroll
            for (int mt = 0; mt < 2; mt++)
                ldsm_x4((sb + a_base[mt]) ^ xv, ah[mt][0], ah[mt][1], ah[mt][2], ah[mt][3]);
            uint32_t bh[8][2];
#pragma unroll
            for (int bt = 0; bt < 4; bt++) {
                uint32_t r0, r1, r2, r3;
                ldsm_x4((sb + b_base[bt]) ^ xv, r0, r1, r2, r3);
                bh[2 * bt][0] = r0; bh[2 * bt][1] = r2;
                bh[2 * bt + 1][0] = r1; bh[2 * bt + 1][1] = r3;
            }
#pragma unroll
            for (int mt = 0; mt < 2; mt++)
#pragma unroll
                for (int nt = 0; nt < 8; nt++)
                    mma16816(acc[mt][nt], ah[mt], bh[nt][0], bh[nt][1]);
        }
    }

    const int ob = (lane & 3) * 2;
#pragma unroll
    for (int mt = 0; mt < 2; mt++) {
#pragma unroll
        for (int half = 0; half < 2; half++) {
            int m = m0 + wm * 32 + mt * 16 + (lane >> 2) + half * 8;
            __half* yp = g_Yh + (size_t)m * 512 + g * NF + wn * 64;
#pragma unroll
            for (int nt = 0; nt < 8; nt++) {
                __half2 hv = __floats2half2_rn(acc[mt][nt][half * 2 + 0],
                                               acc[mt][nt][half * 2 + 1]);
                *(__half2*)&yp[nt * 8 + ob] = hv;
            }
        }
    }
}

// ---------------------------------------------------------------------------
// Combine: inverse twiddle + bias, reading fp16 Y.
// ---------------------------------------------------------------------------
__global__ void combine_kernel(float* __restrict__ out) {
    const int m = blockIdx.x * 8 + (threadIdx.x >> 5);
    if (m >= Mdim) return;
    const int lane = threadIdx.x & 31;

    const __half2* y2 = (const __half2*)(g_Yh + (size_t)m * 512);
    float2 Z0 = __half22float2(y2[lane]);
    float2 Z4 = __half22float2(y2[32 + lane]);
    float2 R1 = __half22float2(y2[64 + lane]);
    float2 I1 = __half22float2(y2[96 + lane]);
    float2 R2 = __half22float2(y2[128 + lane]);
    float2 I2 = __half22float2(y2[160 + lane]);
    float2 R3 = __half22float2(y2[192 + lane]);
    float2 I3 = __half22float2(y2[224 + lane]);

    const float bx = g_biasK[2 * lane];
    const float by = g_biasK[2 * lane + 1];

    const int b = m / Nn;
    const int n = m - b * Nn;
    float* op = out + (size_t)b * ((size_t)KAa * Nn * Oo) + (size_t)n * Oo + 2 * lane;

    const float C1[8] = {1.f, SQH, 0.f, -SQH, -1.f, -SQH, 0.f, SQH};
    const float S1[8] = {0.f, SQH, 1.f, SQH, 0.f, -SQH, -1.f, -SQH};
    const float C2[8] = {1.f, 0.f, -1.f, 0.f, 1.f, 0.f, -1.f, 0.f};
    const float S2[8] = {0.f, 1.f, 0.f, -1.f, 0.f, 1.f, 0.f, -1.f};
    const float C3[8] = {1.f, -SQH, 0.f, SQH, -1.f, SQH, 0.f, -SQH};
    const float S3[8] = {0.f, SQH, -1.f, SQH, 0.f, -SQH, 1.f, -SQH};

#pragma unroll
    for (int r = 0; r < 8; r++) {
        float sg = (r & 1) ? -1.f : 1.f;
        float2 v;
        v.x = 0.125f * (Z0.x + sg * Z4.x)
            + 0.25f * (C1[r] * R1.x - S1[r] * I1.x
                     + C2[r] * R2.x - S2[r] * I2.x
                     + C3[r] * R3.x - S3[r] * I3.x) + bx;
        v.y = 0.125f * (Z0.y + sg * Z4.y)
            + 0.25f * (C1[r] * R1.y - S1[r] * I1.y
                     + C2[r] * R2.y - S2[r] * I2.y
                     + C3[r] * R3.y - S3[r] * I3.y) + by;
        *(float2*)&op[(size_t)r * (Nn * Oo)] = v;
    }
}

// ---------------------------------------------------------------------------
extern "C" void kernel_launch(void* const* d_in, const int* in_sizes, int n_in,
                              void* d_out, int out_size) {
    const float* signal  = (const float*)d_in[0];
    const float* bary    = (const float*)d_in[1];
    const float* kernels = (const float*)d_in[2];
    const float* bias    = (const float*)d_in[3];
    float* out = (float*)d_out;

    conv_signal_kernel<<<(4 * Nn * Cc / 4 + 255) / 256, 256>>>(signal);
    prep_wb_kernel<<<NBLK * NF, KF>>>(kernels);
    prep_bias_kernel<<<1, Oo>>>(bias);

    gather_fft_kernel<<<Mdim / 32, 256>>>(bary);

    {
        static int smem_set = 0;
        if (!smem_set) {
            cudaFuncSetAttribute(gemm_mma_kernel,
                                 cudaFuncAttributeMaxDynamicSharedMemorySize, GEMM_SMEM);
            smem_set = 1;
        }
        dim3 grid(NBLK, Mpad / 128);   // (4, 313)
        gemm_mma_kernel<<<grid, 256, GEMM_SMEM>>>();
    }

    combine_kernel<<<Mdim / 8, 256>>>(out);
}

// round 12
// speedup vs baseline: 1.3149x; 1.0312x over previous
#include <cuda_runtime.h>
#include <cuda_fp16.h>
#include <cstdint>

// ---------------- problem constants ----------------
#define Nn   10000
#define KRr  5
#define KAa  8
#define Cc   32
#define Oo   64

#define Mdim 40000            // B*N
#define Kdim 1280             // KR*KA*C  (X-hat logical row width)
#define Mpad 40064            // 313 * 128

// ---------------- frequency-block GEMM tiling ----------------
#define KF   320                   // K per freq block
#define NF   128                   // N per freq block
#define NBLK 4                     // {f0|f4}, f1, f2, f3
#define KCHUNK 64                  // fp16 per K chunk (128 B per row)
#define NCHUNK_F (KF / KCHUNK)     // 5
#define B_OFF 16384
#define STAGE_BYTES 32768
#define NSTAGE 3
#define GEMM_SMEM (NSTAGE * STAGE_BYTES)   // 98304 -> 2 CTAs/SM

#define SQH 0.70710678118654752f

// ---------------- device scratch ----------------
// X-hat physical layout: [j][m][32] halfs, j = comp*5 + p  (40 blocks)
__device__ __half g_Xh[(size_t)40 * Mpad * 32];
__device__ __half g_Wb[(size_t)NBLK * NF * KF];     // W-hat blocks [4][128][320]
__device__ __half g_Sh[(size_t)4 * Nn * Cc];        // signal fp16
__device__ __half g_Yh[(size_t)Mpad * 512];         // freq-domain GEMM output (fp16)
__device__ float  g_biasK[Oo];

// ---------------- helpers ----------------
__device__ __forceinline__ uint32_t smem_u32(const void* p) {
    uint32_t a;
    asm("{ .reg .u64 t; cvta.to.shared.u64 t, %1; cvt.u32.u64 %0, t; }" : "=r"(a) : "l"(p));
    return a;
}
__device__ __forceinline__ void cp16(uint32_t dst, const void* src) {
    asm volatile("cp.async.cg.shared.global [%0], [%1], 16;" :: "r"(dst), "l"(src));
}
__device__ __forceinline__ void ldsm_x4(uint32_t addr, uint32_t& r0, uint32_t& r1,
                                        uint32_t& r2, uint32_t& r3) {
    asm volatile("ldmatrix.sync.aligned.m8n8.x4.shared.b16 {%0,%1,%2,%3}, [%4];"
                 : "=r"(r0), "=r"(r1), "=r"(r2), "=r"(r3) : "r"(addr));
}
__device__ __forceinline__ void mma16816(float* c, const uint32_t* a,
                                         uint32_t b0, uint32_t b1) {
    asm volatile(
        "mma.sync.aligned.m16n8k16.row.col.f32.f16.f16.f32 "
        "{%0,%1,%2,%3}, {%4,%5,%6,%7}, {%8,%9}, {%0,%1,%2,%3};"
        : "+f"(c[0]), "+f"(c[1]), "+f"(c[2]), "+f"(c[3])
        : "r"(a[0]), "r"(a[1]), "r"(a[2]), "r"(a[3]), "r"(b0), "r"(b1));
}

// 8-point real DFT: x[0..7] -> {X0, X4, Re1, Im1, Re2, Im2, Re3, Im3}
__device__ __forceinline__ void fft8(const float* x, float* o) {
    float p04 = x[0] + x[4], m04 = x[0] - x[4];
    float p26 = x[2] + x[6], m26 = x[2] - x[6];
    float pbd = x[1] + x[3], pfh = x[5] + x[7];
    float mbd = x[1] - x[3], mfh = x[5] - x[7];
    float sodd = pbd + pfh;
    float B1 = mbd - mfh;
    float B2 = pfh - pbd;
    o[0] = p04 + p26 + sodd;
    o[1] = p04 + p26 - sodd;
    o[2] = m04 + SQH * B1;
    o[3] = -m26 + SQH * B2;
    o[4] = p04 - p26;
    o[5] = -(mbd + mfh);
    o[6] = m04 - SQH * B1;
    o[7] = m26 + SQH * B2;
}

// ---------------------------------------------------------------------------
__global__ void conv_signal_kernel(const float* __restrict__ signal) {
    int i = blockIdx.x * blockDim.x + threadIdx.x;
    if (i >= (4 * Nn * Cc) / 4) return;
    float4 v = ((const float4*)signal)[i];
    __half2 h0 = __halves2half2(__float2half_rn(v.x), __float2half_rn(v.y));
    __half2 h1 = __halves2half2(__float2half_rn(v.z), __float2half_rn(v.w));
    ((__half2*)g_Sh)[2 * i]     = h0;
    ((__half2*)g_Sh)[2 * i + 1] = h1;
}

// ---------------------------------------------------------------------------
// Prep W-hat blocks (unchanged)
// ---------------------------------------------------------------------------
__global__ void prep_wb_kernel(const float* __restrict__ kernels) {
    const int row = blockIdx.x;            // 0..511
    const int g = row >> 7;
    const int np = row & 127;
    const int h = np >> 6, o = np & 63;
    const int kp = threadIdx.x;            // 0..319
    const int half = (kp >= 160) ? 1 : 0;
    const int kk = kp - 160 * half;
    const int p = kk >> 5, c = kk & 31;

    float wsum[8];
#pragma unroll
    for (int q = 0; q < 8; q++) {
        int base = p * 16384 + q * 2048 + o * 32 + c;
        wsum[q] = kernels[base] + kernels[81920 + base];
    }

    float val = 0.f;
    if (g == 0) {
        if (h == 0 && half == 0) {
#pragma unroll
            for (int q = 0; q < 8; q++) val += wsum[q];
        } else if (h == 1 && half == 1) {
#pragma unroll
            for (int q = 0; q < 8; q++) val += (q & 1) ? -wsum[q] : wsum[q];
        }
    } else {
        const float ct[8] = {1.f, SQH, 0.f, -SQH, -1.f, -SQH, 0.f, SQH};
        const float st[8] = {0.f, SQH, 1.f, SQH, 0.f, -SQH, -1.f, -SQH};
        float Wr = 0.f, Wi = 0.f;
#pragma unroll
        for (int q = 0; q < 8; q++) {
            int i = (g * q) & 7;
            Wr += wsum[q] * ct[i];
            Wi -= wsum[q] * st[i];
        }
        if (h == 0) val = half ? Wi : Wr;
        else        val = half ? -Wr : Wi;
    }
    g_Wb[(size_t)row * KF + kp] = __float2half_rn(val);
}

__global__ void prep_bias_kernel(const float* __restrict__ bias) {
    int o = threadIdx.x;
    float s = 0.f;
#pragma unroll
    for (int pq = 0; pq < KRr * KAa; pq++) s += bias[pq * Oo + o];
    g_biasK[o] = 2.0f * s;
}

// ---------------------------------------------------------------------------
// Gather + FFT -> X-hat fp16 (layout [j][m][32]); bary staged in SMEM.
// Store per (p,comp): warp writes 256B contiguous (4 consecutive m x 64B).
// ---------------------------------------------------------------------------
__global__ void __launch_bounds__(256)
gather_fft_kernel(const float* __restrict__ bary) {
    __shared__ __align__(16) float sbary[32 * 240];   // 30720 B

    const int tid  = threadIdx.x;
    const int wid  = tid >> 5;
    const int lane = tid & 31;
    const int grp  = lane >> 3;
    const int sub  = lane & 7;

    const int m0blk = blockIdx.x * 32;
    const int ml = wid * 4 + grp;          // local m in [0,32)
    const int m  = m0blk + ml;

    // stage bary block (coalesced)
    {
        const float4* src = (const float4*)(bary + (size_t)m0blk * 240);
        float4* dst = (float4*)sbary;
#pragma unroll
        for (int i = 0; i < 1920 / 256; i++)
            dst[tid + i * 256] = src[tid + i * 256];
        if (tid < 1920 - (1920 / 256) * 256)
            dst[tid + (1920 / 256) * 256] = src[tid + (1920 / 256) * 256];
    }
    __syncthreads();

    const int b = m / Nn;
    const uint2* sb = (const uint2*)(g_Sh + (size_t)b * (Nn * Cc));
    const float2* bm = (const float2*)(sbary + ml * 240);
    uint2* xg = (uint2*)g_Xh;              // [j][m][8] uint2 units

#pragma unroll
    for (int p = 0; p < KRr; p++) {
        float acc[8][4];
#pragma unroll
        for (int q = 0; q < 8; q++) {
            const float2* bb = bm + (p * 8 + q) * 3;
            float a0 = 0.f, a1 = 0.f, a2 = 0.f, a3 = 0.f;
#pragma unroll
            for (int v = 0; v < 3; v++) {
                float2 iw = bb[v];                 // ld.shared.v2 broadcast
                int idx = (int)iw.x;
                uint2 s = sb[idx * 8 + sub];
                float2 f0 = __half22float2(*(const __half2*)&s.x);
                float2 f1 = __half22float2(*(const __half2*)&s.y);
                a0 = fmaf(iw.y, f0.x, a0);
                a1 = fmaf(iw.y, f0.y, a1);
                a2 = fmaf(iw.y, f1.x, a2);
                a3 = fmaf(iw.y, f1.y, a3);
            }
            acc[q][0] = a0; acc[q][1] = a1; acc[q][2] = a2; acc[q][3] = a3;
        }
        float o[4][8];
#pragma unroll
        for (int j = 0; j < 4; j++) {
            float in[8];
#pragma unroll
            for (int q = 0; q < 8; q++) in[q] = acc[q][j];
            fft8(in, o[j]);
        }
#pragma unroll
        for (int comp = 0; comp < 8; comp++) {
            __half2 h0 = __halves2half2(__float2half_rn(o[0][comp]),
                                        __float2half_rn(o[1][comp]));
            __half2 h1 = __halves2half2(__float2half_rn(o[2][comp]),
                                        __float2half_rn(o[3][comp]));
            uint2 v;
            v.x = *(const uint32_t*)&h0;
            v.y = *(const uint32_t*)&h1;
            // j-block = comp*5 + p ; warp writes 256B contiguous
            xg[((size_t)(comp * 5 + p) * Mpad + m) * 8 + sub] = v;
        }
    }
}

// ---------------------------------------------------------------------------
// HMMA GEMM per freq block; A read from [j][m][32] layout; Y written fp16.
// ---------------------------------------------------------------------------
__global__ void __launch_bounds__(256, 2)
gemm_mma_kernel() {
    extern __shared__ __align__(1024) char smem[];
    const uint32_t sb0 = smem_u32(smem);
    const int tid  = threadIdx.x;
    const int wid  = tid >> 5;
    const int lane = tid & 31;
    const int wm = wid & 3;
    const int wn = wid >> 2;

    const int g  = blockIdx.x;
    const int m0 = blockIdx.y * 128;

    const int l_row = tid >> 3;
    const int l_seg = tid & 7;
    const uint32_t l_doff = l_row * 128 + ((l_seg ^ (l_row & 7)) << 4);
    // A source: chunk c, local k-seg l_seg -> j = g*10 + 2c + (l_seg>>2),
    // half offset within 32-half row = (l_seg&3)*8
    const __half* aptr = g_Xh
        + ((size_t)(g * 10 + (l_seg >> 2)) * Mpad + m0 + l_row) * 32
        + (l_seg & 3) * 8;
    const __half* bptr = g_Wb + (size_t)(g * NF + l_row) * KF + l_seg * 8;

    auto load_stage = [&](int c) {
        const uint32_t sb = sb0 + (c % NSTAGE) * STAGE_BYTES;
        const __half* a = aptr + (size_t)(2 * c) * (Mpad * 32);
        const __half* b = bptr + c * KCHUNK;
#pragma unroll
        for (int i = 0; i < 4; i++) {
            uint32_t d = sb + l_doff + i * (32 * 128);
            cp16(d,         a + (size_t)(i * 32) * 32);
            cp16(d + B_OFF, b + (size_t)(i * 32) * KF);
        }
        asm volatile("cp.async.commit_group;" ::: "memory");
    };

    float acc[2][8][4];
#pragma unroll
    for (int mt = 0; mt < 2; mt++)
#pragma unroll
        for (int nt = 0; nt < 8; nt++)
#pragma unroll
            for (int i = 0; i < 4; i++) acc[mt][nt][i] = 0.f;

    const int sel = lane >> 4;
    uint32_t a_base[2], b_base[4];
#pragma unroll
    for (int mt = 0; mt < 2; mt++) {
        int r = wm * 32 + (lane & 15) + mt * 16;
        a_base[mt] = r * 128 + (((sel ^ r) & 7) << 4);
    }
#pragma unroll
    for (int bt = 0; bt < 4; bt++) {
        int r = wn * 64 + (lane & 15) + bt * 16;
        b_base[bt] = B_OFF + r * 128 + (((sel ^ r) & 7) << 4);
    }

    load_stage(0);
    load_stage(1);

    for (int c = 0; c < NCHUNK_F; c++) {
        if (c + 1 < NCHUNK_F) asm volatile("cp.async.wait_group 1;" ::: "memory");
        else                  asm volatile("cp.async.wait_group 0;" ::: "memory");
        __syncthreads();
        if (c + 2 < NCHUNK_F) load_stage(c + 2);

        const uint32_t sb = sb0 + (c % NSTAGE) * STAGE_BYTES;

#pragma unroll
        for (int ks = 0; ks < 4; ks++) {
            const uint32_t xv = ks << 5;
            uint32_t ah[2][4];
#pragma unroll
            for (int mt = 0; mt < 2; mt++)
                ldsm_x4((sb + a_base[mt]) ^ xv, ah[mt][0], ah[mt][1], ah[mt][2], ah[mt][3]);
            uint32_t bh[8][2];
#pragma unroll
            for (int bt = 0; bt < 4; bt++) {
                uint32_t r0, r1, r2, r3;
                ldsm_x4((sb + b_base[bt]) ^ xv, r0, r1, r2, r3);
                bh[2 * bt][0] = r0; bh[2 * bt][1] = r2;
                bh[2 * bt + 1][0] = r1; bh[2 * bt + 1][1] = r3;
            }
#pragma unroll
            for (int mt = 0; mt < 2; mt++)
#pragma unroll
                for (int nt = 0; nt < 8; nt++)
                    mma16816(acc[mt][nt], ah[mt], bh[nt][0], bh[nt][1]);
        }
    }

    const int ob = (lane & 3) * 2;
#pragma unroll
    for (int mt = 0; mt < 2; mt++) {
#pragma unroll
        for (int half = 0; half < 2; half++) {
            int m = m0 + wm * 32 + mt * 16 + (lane >> 2) + half * 8;
            __half* yp = g_Yh + (size_t)m * 512 + g * NF + wn * 64;
#pragma unroll
            for (int nt = 0; nt < 8; nt++) {
                __half2 hv = __floats2half2_rn(acc[mt][nt][half * 2 + 0],
                                               acc[mt][nt][half * 2 + 1]);
                *(__half2*)&yp[nt * 8 + ob] = hv;
            }
        }
    }
}

// ---------------------------------------------------------------------------
// Combine: inverse twiddle + bias, reading fp16 Y.
// ---------------------------------------------------------------------------
__global__ void combine_kernel(float* __restrict__ out) {
    const int m = blockIdx.x * 8 + (threadIdx.x >> 5);
    if (m >= Mdim) return;
    const int lane = threadIdx.x & 31;

    const __half2* y2 = (const __half2*)(g_Yh + (size_t)m * 512);
    float2 Z0 = __half22float2(y2[lane]);
    float2 Z4 = __half22float2(y2[32 + lane]);
    float2 R1 = __half22float2(y2[64 + lane]);
    float2 I1 = __half22float2(y2[96 + lane]);
    float2 R2 = __half22float2(y2[128 + lane]);
    float2 I2 = __half22float2(y2[160 + lane]);
    float2 R3 = __half22float2(y2[192 + lane]);
    float2 I3 = __half22float2(y2[224 + lane]);

    const float bx = g_biasK[2 * lane];
    const float by = g_biasK[2 * lane + 1];

    const int b = m / Nn;
    const int n = m - b * Nn;
    float* op = out + (size_t)b * ((size_t)KAa * Nn * Oo) + (size_t)n * Oo + 2 * lane;

    const float C1[8] = {1.f, SQH, 0.f, -SQH, -1.f, -SQH, 0.f, SQH};
    const float S1[8] = {0.f, SQH, 1.f, SQH, 0.f, -SQH, -1.f, -SQH};
    const float C2[8] = {1.f, 0.f, -1.f, 0.f, 1.f, 0.f, -1.f, 0.f};
    const float S2[8] = {0.f, 1.f, 0.f, -1.f, 0.f, 1.f, 0.f, -1.f};
    const float C3[8] = {1.f, -SQH, 0.f, SQH, -1.f, SQH, 0.f, -SQH};
    const float S3[8] = {0.f, SQH, -1.f, SQH, 0.f, -SQH, 1.f, -SQH};

#pragma unroll
    for (int r = 0; r < 8; r++) {
        float sg = (r & 1) ? -1.f : 1.f;
        float2 v;
        v.x = 0.125f * (Z0.x + sg * Z4.x)
            + 0.25f * (C1[r] * R1.x - S1[r] * I1.x
                     + C2[r] * R2.x - S2[r] * I2.x
                     + C3[r] * R3.x - S3[r] * I3.x) + bx;
        v.y = 0.125f * (Z0.y + sg * Z4.y)
            + 0.25f * (C1[r] * R1.y - S1[r] * I1.y
                     + C2[r] * R2.y - S2[r] * I2.y
                     + C3[r] * R3.y - S3[r] * I3.y) + by;
        *(float2*)&op[(size_t)r * (Nn * Oo)] = v;
    }
}

// ---------------------------------------------------------------------------
extern "C" void kernel_launch(void* const* d_in, const int* in_sizes, int n_in,
                              void* d_out, int out_size) {
    const float* signal  = (const float*)d_in[0];
    const float* bary    = (const float*)d_in[1];
    const float* kernels = (const float*)d_in[2];
    const float* bias    = (const float*)d_in[3];
    float* out = (float*)d_out;

    conv_signal_kernel<<<(4 * Nn * Cc / 4 + 255) / 256, 256>>>(signal);
    prep_wb_kernel<<<NBLK * NF, KF>>>(kernels);
    prep_bias_kernel<<<1, Oo>>>(bias);

    gather_fft_kernel<<<Mdim / 32, 256>>>(bary);

    {
        static int smem_set = 0;
        if (!smem_set) {
            cudaFuncSetAttribute(gemm_mma_kernel,
                                 cudaFuncAttributeMaxDynamicSharedMemorySize, GEMM_SMEM);
            smem_set = 1;
        }
        dim3 grid(NBLK, Mpad / 128);   // (4, 313)
        gemm_mma_kernel<<<grid, 256, GEMM_SMEM>>>();
    }

    combine_kernel<<<Mdim / 8, 256>>>(out);
}

// round 14
// speedup vs baseline: 1.3459x; 1.0236x over previous
#include <cuda_runtime.h>
#include <cuda_fp16.h>
#include <cstdint>

// ---------------- problem constants ----------------
#define Nn   10000
#define KRr  5
#define KAa  8
#define Cc   32
#define Oo   64

#define Mdim 40000            // B*N
#define Mpad 40064            // 313 * 128

// ---------------- frequency-block GEMM tiling ----------------
#define KF   320                   // K per freq block
#define NF   128                   // N per freq block
#define NBLK 4                     // {f0|f4}, f1, f2, f3
#define KCHUNK 64                  // fp16 per K chunk (128 B per row)
#define NCHUNK_F (KF / KCHUNK)     // 5
#define B_OFF 16384
#define STAGE_BYTES 32768
#define NSTAGE 3
#define GEMM_SMEM (NSTAGE * STAGE_BYTES)   // 98304 -> 2 CTAs/SM

#define SQH 0.70710678118654752f

// ---------------- device scratch ----------------
// X-hat physical layout: [j][m][32] halfs, j = comp*5 + p  (40 blocks)
__device__ __half g_Xh[(size_t)40 * Mpad * 32];
__device__ __half g_Wb[(size_t)NBLK * NF * KF];     // W-hat blocks [4][128][320]
__device__ __half g_Sh[(size_t)4 * Nn * Cc];        // signal fp16
__device__ __half g_Yh[(size_t)Mpad * 512];         // freq-domain GEMM output (fp16)
__device__ float  g_biasK[Oo];

// ---------------- helpers ----------------
__device__ __forceinline__ uint32_t smem_u32(const void* p) {
    uint32_t a;
    asm("{ .reg .u64 t; cvta.to.shared.u64 t, %1; cvt.u32.u64 %0, t; }" : "=r"(a) : "l"(p));
    return a;
}
__device__ __forceinline__ void cp16(uint32_t dst, const void* src) {
    asm volatile("cp.async.cg.shared.global [%0], [%1], 16;" :: "r"(dst), "l"(src));
}
__device__ __forceinline__ void ldsm_x4(uint32_t addr, uint32_t& r0, uint32_t& r1,
                                        uint32_t& r2, uint32_t& r3) {
    asm volatile("ldmatrix.sync.aligned.m8n8.x4.shared.b16 {%0,%1,%2,%3}, [%4];"
                 : "=r"(r0), "=r"(r1), "=r"(r2), "=r"(r3) : "r"(addr));
}
__device__ __forceinline__ void mma16816(float* c, const uint32_t* a,
                                         uint32_t b0, uint32_t b1) {
    asm volatile(
        "mma.sync.aligned.m16n8k16.row.col.f32.f16.f16.f32 "
        "{%0,%1,%2,%3}, {%4,%5,%6,%7}, {%8,%9}, {%0,%1,%2,%3};"
        : "+f"(c[0]), "+f"(c[1]), "+f"(c[2]), "+f"(c[3])
        : "r"(a[0]), "r"(a[1]), "r"(a[2]), "r"(a[3]), "r"(b0), "r"(b1));
}

// 8-point real DFT: x[0..7] -> {X0, X4, Re1, Im1, Re2, Im2, Re3, Im3}
__device__ __forceinline__ void fft8(const float* x, float* o) {
    float p04 = x[0] + x[4], m04 = x[0] - x[4];
    float p26 = x[2] + x[6], m26 = x[2] - x[6];
    float pbd = x[1] + x[3], pfh = x[5] + x[7];
    float mbd = x[1] - x[3], mfh = x[5] - x[7];
    float sodd = pbd + pfh;
    float B1 = mbd - mfh;
    float B2 = pfh - pbd;
    o[0] = p04 + p26 + sodd;
    o[1] = p04 + p26 - sodd;
    o[2] = m04 + SQH * B1;
    o[3] = -m26 + SQH * B2;
    o[4] = p04 - p26;
    o[5] = -(mbd + mfh);
    o[6] = m04 - SQH * B1;
    o[7] = m26 + SQH * B2;
}

// ---------------------------------------------------------------------------
// Merged prep: blocks 0..511 -> W-hat rows (+bias on block 0);
//              blocks 512..1511 -> signal fp16 conversion (320000 float4).
// 320 threads/block.
// ---------------------------------------------------------------------------
__global__ void __launch_bounds__(320)
prep_all_kernel(const float* __restrict__ signal,
                const float* __restrict__ kernels,
                const float* __restrict__ bias) {
    const int blk = blockIdx.x;
    if (blk < 512) {
        const int row = blk;                  // 0..511
        const int g = row >> 7;
        const int np = row & 127;
        const int h = np >> 6, o = np & 63;
        const int kp = threadIdx.x;           // 0..319
        const int half = (kp >= 160) ? 1 : 0;
        const int kk = kp - 160 * half;
        const int p = kk >> 5, c = kk & 31;

        float wsum[8];
#pragma unroll
        for (int q = 0; q < 8; q++) {
            int base = p * 16384 + q * 2048 + o * 32 + c;
            wsum[q] = kernels[base] + kernels[81920 + base];
        }

        float val = 0.f;
        if (g == 0) {
            if (h == 0 && half == 0) {
#pragma unroll
                for (int q = 0; q < 8; q++) val += wsum[q];
            } else if (h == 1 && half == 1) {
#pragma unroll
                for (int q = 0; q < 8; q++) val += (q & 1) ? -wsum[q] : wsum[q];
            }
        } else {
            const float ct[8] = {1.f, SQH, 0.f, -SQH, -1.f, -SQH, 0.f, SQH};
            const float st[8] = {0.f, SQH, 1.f, SQH, 0.f, -SQH, -1.f, -SQH};
            float Wr = 0.f, Wi = 0.f;
#pragma unroll
            for (int q = 0; q < 8; q++) {
                int i = (g * q) & 7;
                Wr += wsum[q] * ct[i];
                Wi -= wsum[q] * st[i];
            }
            if (h == 0) val = half ? Wi : Wr;
            else        val = half ? -Wr : Wi;
        }
        g_Wb[(size_t)row * KF + kp] = __float2half_rn(val);

        if (blk == 0 && threadIdx.x < 64) {
            int oo = threadIdx.x;
            float s = 0.f;
#pragma unroll
            for (int pq = 0; pq < KRr * KAa; pq++) s += bias[pq * Oo + oo];
            g_biasK[oo] = 2.0f * s;
        }
    } else {
        int i = (blk - 512) * 320 + threadIdx.x;          // float4 index
        if (i < (4 * Nn * Cc) / 4) {
            float4 v = ((const float4*)signal)[i];
            __half2 h0 = __halves2half2(__float2half_rn(v.x), __float2half_rn(v.y));
            __half2 h1 = __halves2half2(__float2half_rn(v.z), __float2half_rn(v.w));
            ((__half2*)g_Sh)[2 * i]     = h0;
            ((__half2*)g_Sh)[2 * i + 1] = h1;
        }
    }
}

// ---------------------------------------------------------------------------
// Gather + FFT -> X-hat fp16 (layout [j][m][32]); bary staged in SMEM.
// __launch_bounds__(256,4): cap regs to restore occupancy (latency-bound).
// ---------------------------------------------------------------------------
__global__ void __launch_bounds__(256, 4)
gather_fft_kernel(const float* __restrict__ bary) {
    __shared__ __align__(16) float sbary[32 * 240];   // 30720 B

    const int tid  = threadIdx.x;
    const int wid  = tid >> 5;
    const int lane = tid & 31;
    const int grp  = lane >> 3;
    const int sub  = lane & 7;

    const int m0blk = blockIdx.x * 32;
    const int ml = wid * 4 + grp;          // local m in [0,32)
    const int m  = m0blk + ml;

    // stage bary block (coalesced)
    {
        const float4* src = (const float4*)(bary + (size_t)m0blk * 240);
        float4* dst = (float4*)sbary;
#pragma unroll
        for (int i = 0; i < 1920 / 256; i++)
            dst[tid + i * 256] = src[tid + i * 256];
        if (tid < 1920 - (1920 / 256) * 256)
            dst[tid + (1920 / 256) * 256] = src[tid + (1920 / 256) * 256];
    }
    __syncthreads();

    const int b = m / Nn;
    const uint2* sb = (const uint2*)(g_Sh + (size_t)b * (Nn * Cc));
    const float2* bm = (const float2*)(sbary + ml * 240);
    uint2* xg = (uint2*)g_Xh;              // [j][m][8] uint2 units

#pragma unroll
    for (int p = 0; p < KRr; p++) {
        float acc[8][4];
#pragma unroll
        for (int q = 0; q < 8; q++) {
            const float2* bb = bm + (p * 8 + q) * 3;
            float a0 = 0.f, a1 = 0.f, a2 = 0.f, a3 = 0.f;
#pragma unroll
            for (int v = 0; v < 3; v++) {
                float2 iw = bb[v];                 // ld.shared.v2 broadcast
                int idx = (int)iw.x;
                uint2 s = sb[idx * 8 + sub];
                float2 f0 = __half22float2(*(const __half2*)&s.x);
                float2 f1 = __half22float2(*(const __half2*)&s.y);
                a0 = fmaf(iw.y, f0.x, a0);
                a1 = fmaf(iw.y, f0.y, a1);
                a2 = fmaf(iw.y, f1.x, a2);
                a3 = fmaf(iw.y, f1.y, a3);
            }
            acc[q][0] = a0; acc[q][1] = a1; acc[q][2] = a2; acc[q][3] = a3;
        }
        float o[4][8];
#pragma unroll
        for (int j = 0; j < 4; j++) {
            float in[8];
#pragma unroll
            for (int q = 0; q < 8; q++) in[q] = acc[q][j];
            fft8(in, o[j]);
        }
#pragma unroll
        for (int comp = 0; comp < 8; comp++) {
            __half2 h0 = __halves2half2(__float2half_rn(o[0][comp]),
                                        __float2half_rn(o[1][comp]));
            __half2 h1 = __halves2half2(__float2half_rn(o[2][comp]),
                                        __float2half_rn(o[3][comp]));
            uint2 v;
            v.x = *(const uint32_t*)&h0;
            v.y = *(const uint32_t*)&h1;
            xg[((size_t)(comp * 5 + p) * Mpad + m) * 8 + sub] = v;
        }
    }
}

// ---------------------------------------------------------------------------
// HMMA GEMM per freq block; A read from [j][m][32] layout; Y written fp16.
// ---------------------------------------------------------------------------
__global__ void __launch_bounds__(256, 2)
gemm_mma_kernel() {
    extern __shared__ __align__(1024) char smem[];
    const uint32_t sb0 = smem_u32(smem);
    const int tid  = threadIdx.x;
    const int wid  = tid >> 5;
    const int lane = tid & 31;
    const int wm = wid & 3;
    const int wn = wid >> 2;

    const int g  = blockIdx.x;
    const int m0 = blockIdx.y * 128;

    const int l_row = tid >> 3;
    const int l_seg = tid & 7;
    const uint32_t l_doff = l_row * 128 + ((l_seg ^ (l_row & 7)) << 4);
    const __half* aptr = g_Xh
        + ((size_t)(g * 10 + (l_seg >> 2)) * Mpad + m0 + l_row) * 32
        + (l_seg & 3) * 8;
    const __half* bptr = g_Wb + (size_t)(g * NF + l_row) * KF + l_seg * 8;

    auto load_stage = [&](int c) {
        const uint32_t sb = sb0 + (c % NSTAGE) * STAGE_BYTES;
        const __half* a = aptr + (size_t)(2 * c) * (Mpad * 32);
        const __half* b = bptr + c * KCHUNK;
#pragma unroll
        for (int i = 0; i < 4; i++) {
            uint32_t d = sb + l_doff + i * (32 * 128);
            cp16(d,         a + (size_t)(i * 32) * 32);
            cp16(d + B_OFF, b + (size_t)(i * 32) * KF);
        }
        asm volatile("cp.async.commit_group;" ::: "memory");
    };

    float acc[2][8][4];
#pragma unroll
    for (int mt = 0; mt < 2; mt++)
#pragma unroll
        for (int nt = 0; nt < 8; nt++)
#pragma unroll
            for (int i = 0; i < 4; i++) acc[mt][nt][i] = 0.f;

    const int sel = lane >> 4;
    uint32_t a_base[2], b_base[4];
#pragma unroll
    for (int mt = 0; mt < 2; mt++) {
        int r = wm * 32 + (lane & 15) + mt * 16;
        a_base[mt] = r * 128 + (((sel ^ r) & 7) << 4);
    }
#pragma unroll
    for (int bt = 0; bt < 4; bt++) {
        int r = wn * 64 + (lane & 15) + bt * 16;
        b_base[bt] = B_OFF + r * 128 + (((sel ^ r) & 7) << 4);
    }

    load_stage(0);
    load_stage(1);

    for (int c = 0; c < NCHUNK_F; c++) {
        if (c + 1 < NCHUNK_F) asm volatile("cp.async.wait_group 1;" ::: "memory");
        else                  asm volatile("cp.async.wait_group 0;" ::: "memory");
        __syncthreads();
        if (c + 2 < NCHUNK_F) load_stage(c + 2);

        const uint32_t sb = sb0 + (c % NSTAGE) * STAGE_BYTES;

#pragma unroll
        for (int ks = 0; ks < 4; ks++) {
            const uint32_t xv = ks << 5;
            uint32_t ah[2][4];
#pragma unroll
            for (int mt = 0; mt < 2; mt++)
                ldsm_x4((sb + a_base[mt]) ^ xv, ah[mt][0], ah[mt][1], ah[mt][2], ah[mt][3]);
            uint32_t bh[8][2];
#pragma unroll
            for (int bt = 0; bt < 4; bt++) {
                uint32_t r0, r1, r2, r3;
                ldsm_x4((sb + b_base[bt]) ^ xv, r0, r1, r2, r3);
                bh[2 * bt][0] = r0; bh[2 * bt][1] = r2;
                bh[2 * bt + 1][0] = r1; bh[2 * bt + 1][1] = r3;
            }
#pragma unroll
            for (int mt = 0; mt < 2; mt++)
#pragma unroll
                for (int nt = 0; nt < 8; nt++)
                    mma16816(acc[mt][nt], ah[mt], bh[nt][0], bh[nt][1]);
        }
    }

    const int ob = (lane & 3) * 2;
#pragma unroll
    for (int mt = 0; mt < 2; mt++) {
#pragma unroll
        for (int half = 0; half < 2; half++) {
            int m = m0 + wm * 32 + mt * 16 + (lane >> 2) + half * 8;
            __half* yp = g_Yh + (size_t)m * 512 + g * NF + wn * 64;
#pragma unroll
            for (int nt = 0; nt < 8; nt++) {
                __half2 hv = __floats2half2_rn(acc[mt][nt][half * 2 + 0],
                                               acc[mt][nt][half * 2 + 1]);
                *(__half2*)&yp[nt * 8 + ob] = hv;
            }
        }
    }
}

// ---------------------------------------------------------------------------
// Combine: inverse twiddle + bias, reading fp16 Y.
// ---------------------------------------------------------------------------
__global__ void combine_kernel(float* __restrict__ out) {
    const int m = blockIdx.x * 8 + (threadIdx.x >> 5);
    if (m >= Mdim) return;
    const int lane = threadIdx.x & 31;

    const __half2* y2 = (const __half2*)(g_Yh + (size_t)m * 512);
    float2 Z0 = __half22float2(y2[lane]);
    float2 Z4 = __half22float2(y2[32 + lane]);
    float2 R1 = __half22float2(y2[64 + lane]);
    float2 I1 = __half22float2(y2[96 + lane]);
    float2 R2 = __half22float2(y2[128 + lane]);
    float2 I2 = __half22float2(y2[160 + lane]);
    float2 R3 = __half22float2(y2[192 + lane]);
    float2 I3 = __half22float2(y2[224 + lane]);

    const float bx = g_biasK[2 * lane];
    const float by = g_biasK[2 * lane + 1];

    const int b = m / Nn;
    const int n = m - b * Nn;
    float* op = out + (size_t)b * ((size_t)KAa * Nn * Oo) + (size_t)n * Oo + 2 * lane;

    const float C1[8] = {1.f, SQH, 0.f, -SQH, -1.f, -SQH, 0.f, SQH};
    const float S1[8] = {0.f, SQH, 1.f, SQH, 0.f, -SQH, -1.f, -SQH};
    const float C2[8] = {1.f, 0.f, -1.f, 0.f, 1.f, 0.f, -1.f, 0.f};
    const float S2[8] = {0.f, 1.f, 0.f, -1.f, 0.f, 1.f, 0.f, -1.f};
    const float C3[8] = {1.f, -SQH, 0.f, SQH, -1.f, SQH, 0.f, -SQH};
    const float S3[8] = {0.f, SQH, -1.f, SQH, 0.f, -SQH, 1.f, -SQH};

#pragma unroll
    for (int r = 0; r < 8; r++) {
        float sg = (r & 1) ? -1.f : 1.f;
        float2 v;
        v.x = 0.125f * (Z0.x + sg * Z4.x)
            + 0.25f * (C1[r] * R1.x - S1[r] * I1.x
                     + C2[r] * R2.x - S2[r] * I2.x
                     + C3[r] * R3.x - S3[r] * I3.x) + bx;
        v.y = 0.125f * (Z0.y + sg * Z4.y)
            + 0.25f * (C1[r] * R1.y - S1[r] * I1.y
                     + C2[r] * R2.y - S2[r] * I2.y
                     + C3[r] * R3.y - S3[r] * I3.y) + by;
        *(float2*)&op[(size_t)r * (Nn * Oo)] = v;
    }
}

// ---------------------------------------------------------------------------
extern "C" void kernel_launch(void* const* d_in, const int* in_sizes, int n_in,
                              void* d_out, int out_size) {
    const float* signal  = (const float*)d_in[0];
    const float* bary    = (const float*)d_in[1];
    const float* kernels = (const float*)d_in[2];
    const float* bias    = (const float*)d_in[3];
    float* out = (float*)d_out;

    // merged preps: 512 wb blocks + 1000 signal-conversion blocks (320000 float4)
    prep_all_kernel<<<512 + 1000, 320>>>(signal, kernels, bias);

    gather_fft_kernel<<<Mdim / 32, 256>>>(bary);

    {
        static int smem_set = 0;
        if (!smem_set) {
            cudaFuncSetAttribute(gemm_mma_kernel,
                                 cudaFuncAttributeMaxDynamicSharedMemorySize, GEMM_SMEM);
            smem_set = 1;
        }
        dim3 grid(NBLK, Mpad / 128);   // (4, 313)
        gemm_mma_kernel<<<grid, 256, GEMM_SMEM>>>();
    }

    combine_kernel<<<Mdim / 8, 256>>>(out);
}